// round 7
// baseline (speedup 1.0000x reference)
#include <cuda_runtime.h>
#include <cuda_bf16.h>

#define N_NODES 50000
#define E_EDGES 800000
#define IN_C    16
#define HDIM    64
#define HH      32
#define NLAYERS 3
#define FULL    0xffffffffu

// Scratch (device globals)
__device__ float  g_h[N_NODES * HDIM];   // row-major [n][64]
__device__ float4 g_p4[N_NODES * 8];     // row-major [n][32]
__device__ float4 g_q4[N_NODES * 8];     // row-major [n][32] raw relu sums
__device__ int    g_deg[N_NODES];
__device__ int    g_start[N_NODES];
__device__ int    g_cursor[N_NODES];
__device__ int    g_total;
__device__ float4 g_eperm[E_EDGES];      // [src_bits, e0, e1, e2] sorted by dst
__device__ int    g_edst[E_EDGES];       // dst per sorted edge

__device__ __forceinline__ void red_add_v4(float* ptr, float4 v) {
    asm volatile("red.global.add.v4.f32 [%0], {%1,%2,%3,%4};"
                 :: "l"(ptr), "f"(v.x), "f"(v.y), "f"(v.z), "f"(v.w) : "memory");
}

// ---------------- encoder: h + p0 + zero q/deg/total ----------------
__global__ __launch_bounds__(256) void encoder_kernel(
    const float* __restrict__ x,  const float* __restrict__ w,
    const float* __restrict__ b,  const float* __restrict__ g,
    const float* __restrict__ beta,
    const float* __restrict__ w1, const float* __restrict__ b1)
{
    if (blockIdx.x == 0 && threadIdx.x == 0) g_total = 0;
    int warp = (blockIdx.x * blockDim.x + threadIdx.x) >> 5;
    int lane = threadIdx.x & 31;
    int n0   = warp * 4;
    if (n0 >= N_NODES) return;

    float* g_p = (float*)g_p4;
    float* g_q = (float*)g_q4;

    float xv[4], a0[4], a1[4];
#pragma unroll
    for (int i = 0; i < 4; i++) {
        xv[i] = (lane < IN_C) ? x[(n0 + i) * IN_C + lane] : 0.0f;
        a0[i] = __ldg(&b[lane]);
        a1[i] = __ldg(&b[lane + 32]);
    }
#pragma unroll
    for (int k = 0; k < IN_C; k++) {
        float w0 = __ldg(&w[k * HDIM + lane]);
        float w1v = __ldg(&w[k * HDIM + 32 + lane]);
#pragma unroll
        for (int i = 0; i < 4; i++) {
            float xk = __shfl_sync(FULL, xv[i], k);
            a0[i] = fmaf(xk, w0, a0[i]);
            a1[i] = fmaf(xk, w1v, a1[i]);
        }
    }
    float gl = __ldg(&g[lane]), gh = __ldg(&g[lane + 32]);
    float bl = __ldg(&beta[lane]), bh = __ldg(&beta[lane + 32]);
    float h0[4], h1[4];
#pragma unroll
    for (int i = 0; i < 4; i++) {
        float s1 = a0[i] + a1[i], s2 = a0[i] * a0[i] + a1[i] * a1[i];
#pragma unroll
        for (int o = 16; o; o >>= 1) {
            s1 += __shfl_xor_sync(FULL, s1, o);
            s2 += __shfl_xor_sync(FULL, s2, o);
        }
        float mu  = s1 * (1.0f / 64.0f);
        float var = s2 * (1.0f / 64.0f) - mu * mu;
        float rs  = rsqrtf(var + 1e-5f);
        h0[i] = fmaxf(fmaf((a0[i] - mu) * rs, gl, bl), 0.0f);
        h1[i] = fmaxf(fmaf((a1[i] - mu) * rs, gh, bh), 0.0f);
        g_h[(n0 + i) * HDIM + lane]      = h0[i];
        g_h[(n0 + i) * HDIM + 32 + lane] = h1[i];
    }
    float acc[4];
#pragma unroll
    for (int i = 0; i < 4; i++) acc[i] = __ldg(&b1[lane]);
#pragma unroll
    for (int k = 0; k < 32; k++) {
        float wk = __ldg(&w1[k * HH + lane]);
#pragma unroll
        for (int i = 0; i < 4; i++)
            acc[i] = fmaf(__shfl_sync(FULL, h0[i], k), wk, acc[i]);
    }
#pragma unroll
    for (int k = 0; k < 32; k++) {
        float wk = __ldg(&w1[(32 + k) * HH + lane]);
#pragma unroll
        for (int i = 0; i < 4; i++)
            acc[i] = fmaf(__shfl_sync(FULL, h1[i], k), wk, acc[i]);
    }
#pragma unroll
    for (int i = 0; i < 4; i++) {
        g_p[(n0 + i) * HH + lane] = acc[i];
        g_q[(n0 + i) * HH + lane] = 0.0f;
    }
    if (lane < 4) g_deg[n0 + lane] = 0;
}

// ---------------- CSR build ----------------
__global__ void count_kernel(const int* __restrict__ ei) {
    int e = blockIdx.x * blockDim.x + threadIdx.x;
    if (e < E_EDGES) atomicAdd(&g_deg[ei[E_EDGES + e]], 1);
}

__global__ void assign_kernel() {
    int n = blockIdx.x * blockDim.x + threadIdx.x;
    if (n >= N_NODES) return;
    int d = g_deg[n];
    int s = (d > 0) ? atomicAdd(&g_total, d) : 0;
    g_start[n]  = s;
    g_cursor[n] = s;
}

__global__ void bucket_kernel(const int* __restrict__ ei, const float* __restrict__ ea) {
    int e = blockIdx.x * blockDim.x + threadIdx.x;
    if (e >= E_EDGES) return;
    int src = __ldg(&ei[e]);
    int dst = __ldg(&ei[E_EDGES + e]);
    int pos = atomicAdd(&g_cursor[dst], 1);
    g_eperm[pos] = make_float4(__int_as_float(src),
                               __ldg(&ea[e * 3 + 0]),
                               __ldg(&ea[e * 3 + 1]),
                               __ldg(&ea[e * 3 + 2]));
    g_edst[pos] = dst;
}

// ---- edge kernel: dst-sorted, warp-segmented reduction, RED once per run ----
__global__ __launch_bounds__(256) void edge_seg_kernel(const float* __restrict__ w1)
{
    int warp = (blockIdx.x * blockDim.x + threadIdx.x) >> 5;
    int lane = threadIdx.x & 31;
    int grp = lane >> 3, quad = lane & 7;
    int e = warp * 4 + grp;

    const float4* W = (const float4*)(w1 + 64 * HH);
    float4 wa = __ldg(&W[quad]);
    float4 wb = __ldg(&W[8 + quad]);
    float4 wc = __ldg(&W[16 + quad]);

    float4 v = make_float4(0.f, 0.f, 0.f, 0.f);
    int d = -1;
    bool valid = (e < E_EDGES);
    if (valid) {
        float4 m = __ldg(&g_eperm[e]);
        d = __ldg(&g_edst[e]);
        int src = __float_as_int(m.x);
        float4 p = __ldg(&g_p4[src * 8 + quad]);
        v.x = fmaxf(fmaf(m.w, wc.x, fmaf(m.z, wb.x, fmaf(m.y, wa.x, p.x))), 0.f);
        v.y = fmaxf(fmaf(m.w, wc.y, fmaf(m.z, wb.y, fmaf(m.y, wa.y, p.y))), 0.f);
        v.z = fmaxf(fmaf(m.w, wc.z, fmaf(m.z, wb.z, fmaf(m.y, wa.z, p.z))), 0.f);
        v.w = fmaxf(fmaf(m.w, wc.w, fmaf(m.z, wb.w, fmaf(m.y, wa.w, p.w))), 0.f);
    }

    // segmented suffix-sum across the 4 groups (keys sorted => correct)
    {
        int   d1  = __shfl_down_sync(FULL, d, 8);
        float ax = __shfl_down_sync(FULL, v.x, 8);
        float ay = __shfl_down_sync(FULL, v.y, 8);
        float az = __shfl_down_sync(FULL, v.z, 8);
        float aw = __shfl_down_sync(FULL, v.w, 8);
        if (grp < 3 && d1 == d) { v.x += ax; v.y += ay; v.z += az; v.w += aw; }
        int   d2  = __shfl_down_sync(FULL, d, 16);
        float bx = __shfl_down_sync(FULL, v.x, 16);
        float by = __shfl_down_sync(FULL, v.y, 16);
        float bz = __shfl_down_sync(FULL, v.z, 16);
        float bw = __shfl_down_sync(FULL, v.w, 16);
        if (grp < 2 && d2 == d) { v.x += bx; v.y += by; v.z += bz; v.w += bw; }
    }
    // flush: group 0 always (partial run continuing from prev warp is fine
    // because RED is atomic); other groups only if they start a new run
    int dprev = __shfl_up_sync(FULL, d, 8);
    bool flush = valid && (grp == 0 || d != dprev);
    if (flush) red_add_v4((float*)&g_q4[d * 8 + quad], v);
}

// ---- stage-2 + mean + residual + LN; q re-zeroed; LAST fuses heads ----
template<bool LAST>
__global__ __launch_bounds__(256) void node_agg_kernel(
    const float* __restrict__ w2,  const float* __restrict__ b2,
    const float* __restrict__ g,   const float* __restrict__ beta,
    const float* __restrict__ w1n, const float* __restrict__ b1n,
    const float* __restrict__ dw1, const float* __restrict__ db1,
    const float* __restrict__ dw2, const float* __restrict__ db2,
    const float* __restrict__ vw1, const float* __restrict__ vb1,
    const float* __restrict__ vw2, const float* __restrict__ vb2,
    float* __restrict__ out)
{
    __shared__ float sbuf[64 * 36];   // [k][node], stride 36
    int t = threadIdx.x, w = t >> 5, lane = t & 31;
    int n0 = blockIdx.x * 32;
    int rem = N_NODES - n0; if (rem > 32) rem = 32;

    // stage q transposed; zero q behind us
    {
        int nl = t >> 3, k0 = (t & 7) << 2;
        float4 v = make_float4(0.f, 0.f, 0.f, 0.f);
        float4* qp = (float4*)g_q4 + (size_t)n0 * 8 + t;
        if (nl < rem) { v = *qp; *qp = make_float4(0.f, 0.f, 0.f, 0.f); }
        sbuf[(k0 + 0) * 36 + nl] = v.x;
        sbuf[(k0 + 1) * 36 + nl] = v.y;
        sbuf[(k0 + 2) * 36 + nl] = v.z;
        sbuf[(k0 + 3) * 36 + nl] = v.w;
    }
    __syncthreads();

    int nb = w * 4;

    float o0[4] = {0, 0, 0, 0}, o1[4] = {0, 0, 0, 0};
#pragma unroll
    for (int k = 0; k < 32; k++) {
        float4 qv = *(const float4*)&sbuf[k * 36 + nb];
        float wlo = __ldg(&w2[k * HDIM + lane]);
        float whi = __ldg(&w2[k * HDIM + 32 + lane]);
        o0[0] = fmaf(qv.x, wlo, o0[0]); o1[0] = fmaf(qv.x, whi, o1[0]);
        o0[1] = fmaf(qv.y, wlo, o0[1]); o1[1] = fmaf(qv.y, whi, o1[1]);
        o0[2] = fmaf(qv.z, wlo, o0[2]); o1[2] = fmaf(qv.z, whi, o1[2]);
        o0[3] = fmaf(qv.w, wlo, o0[3]); o1[3] = fmaf(qv.w, whi, o1[3]);
    }
    float b2l = __ldg(&b2[lane]),  b2h = __ldg(&b2[32 + lane]);
    float gl  = __ldg(&g[lane]),   gh  = __ldg(&g[lane + 32]);
    float bl  = __ldg(&beta[lane]), bh = __ldg(&beta[lane + 32]);

    float h0[4], h1[4];
#pragma unroll
    for (int i = 0; i < 4; i++) {
        int n = n0 + nb + i;
        bool act = (nb + i) < rem;
        int   dg  = act ? g_deg[n] : 0;
        float inv = (dg > 0) ? (1.f / (float)dg) : 0.f;
        float has = (dg > 0) ? 1.f : 0.f;
        float hh0 = act ? g_h[(size_t)n * HDIM + lane] : 0.f;
        float hh1 = act ? g_h[(size_t)n * HDIM + 32 + lane] : 0.f;
        float a0 = hh0 + o0[i] * inv + has * b2l;
        float a1 = hh1 + o1[i] * inv + has * b2h;
        float s1 = a0 + a1, s2 = a0 * a0 + a1 * a1;
#pragma unroll
        for (int o = 16; o; o >>= 1) {
            s1 += __shfl_xor_sync(FULL, s1, o);
            s2 += __shfl_xor_sync(FULL, s2, o);
        }
        float mu  = s1 * (1.f / 64.f);
        float var = s2 * (1.f / 64.f) - mu * mu;
        float rs  = rsqrtf(var + 1e-5f);
        h0[i] = fmaf((a0 - mu) * rs, gl, bl);
        h1[i] = fmaf((a1 - mu) * rs, gh, bh);
        if (!LAST && act) {
            g_h[(size_t)n * HDIM + lane]      = h0[i];
            g_h[(size_t)n * HDIM + 32 + lane] = h1[i];
        }
    }
    __syncthreads();

#pragma unroll
    for (int i = 0; i < 4; i++) {
        sbuf[lane * 36 + nb + i]        = h0[i];
        sbuf[(lane + 32) * 36 + nb + i] = h1[i];
    }
    __syncthreads();

    if (!LAST) {
        float pacc[4];
        float bb = __ldg(&b1n[lane]);
#pragma unroll
        for (int i = 0; i < 4; i++) pacc[i] = bb;
#pragma unroll
        for (int k = 0; k < 64; k++) {
            float4 hv = *(const float4*)&sbuf[k * 36 + nb];
            float wk = __ldg(&w1n[k * HH + lane]);
            pacc[0] = fmaf(hv.x, wk, pacc[0]);
            pacc[1] = fmaf(hv.y, wk, pacc[1]);
            pacc[2] = fmaf(hv.z, wk, pacc[2]);
            pacc[3] = fmaf(hv.w, wk, pacc[3]);
        }
        float* gp = (float*)g_p4;
#pragma unroll
        for (int i = 0; i < 4; i++)
            if ((nb + i) < rem) gp[(size_t)(n0 + nb + i) * HH + lane] = pacc[i];
    } else {
        float da[4], va[4];
        float dbi = __ldg(&db1[lane]), vbi = __ldg(&vb1[lane]);
#pragma unroll
        for (int i = 0; i < 4; i++) { da[i] = dbi; va[i] = vbi; }
#pragma unroll
        for (int k = 0; k < 64; k++) {
            float4 hv = *(const float4*)&sbuf[k * 36 + nb];
            float dwk = __ldg(&dw1[k * HH + lane]);
            float vwk = __ldg(&vw1[k * HH + lane]);
            da[0] = fmaf(hv.x, dwk, da[0]); va[0] = fmaf(hv.x, vwk, va[0]);
            da[1] = fmaf(hv.y, dwk, da[1]); va[1] = fmaf(hv.y, vwk, va[1]);
            da[2] = fmaf(hv.z, dwk, da[2]); va[2] = fmaf(hv.z, vwk, va[2]);
            da[3] = fmaf(hv.w, dwk, da[3]); va[3] = fmaf(hv.w, vwk, va[3]);
        }
        float w2d  = __ldg(&dw2[lane]);
        float w2v0 = __ldg(&vw2[lane * 2 + 0]);
        float w2v1 = __ldg(&vw2[lane * 2 + 1]);
#pragma unroll
        for (int i = 0; i < 4; i++) {
            float rd = fmaxf(da[i], 0.f), rv = fmaxf(va[i], 0.f);
            float d  = rd * w2d;
            float v0 = rv * w2v0;
            float v1 = rv * w2v1;
#pragma unroll
            for (int o = 16; o; o >>= 1) {
                d  += __shfl_xor_sync(FULL, d, o);
                v0 += __shfl_xor_sync(FULL, v0, o);
                v1 += __shfl_xor_sync(FULL, v1, o);
            }
            int n = n0 + nb + i;
            if (lane == 0 && (nb + i) < rem) {
                out[n] = d + __ldg(&db2[0]);
                float2* vout = (float2*)(out + N_NODES);
                vout[n] = make_float2(v0 + __ldg(&vb2[0]), v1 + __ldg(&vb2[1]));
            }
        }
    }
}

// ---------------- launch ----------------
extern "C" void kernel_launch(void* const* d_in, const int* in_sizes, int n_in,
                              void* d_out, int out_size)
{
    const float* x       = (const float*)d_in[0];
    const int*   ei      = (const int*)  d_in[1];
    const float* ea      = (const float*)d_in[2];
    const float* enc_w   = (const float*)d_in[3];
    const float* enc_b   = (const float*)d_in[4];
    const float* enc_g   = (const float*)d_in[5];
    const float* enc_bt  = (const float*)d_in[6];
    const float* mlp_w1  = (const float*)d_in[7];   // [L, 67, 32]
    const float* mlp_b1  = (const float*)d_in[8];   // [L, 32]
    const float* mlp_w2  = (const float*)d_in[9];   // [L, 32, 64]
    const float* mlp_b2  = (const float*)d_in[10];  // [L, 64]
    const float* ln_g    = (const float*)d_in[11];  // [L, 64]
    const float* ln_b    = (const float*)d_in[12];  // [L, 64]
    const float* dw1     = (const float*)d_in[13];
    const float* db1     = (const float*)d_in[14];
    const float* dw2     = (const float*)d_in[15];
    const float* db2     = (const float*)d_in[16];
    const float* vw1     = (const float*)d_in[17];
    const float* vb1     = (const float*)d_in[18];
    const float* vw2     = (const float*)d_in[19];
    const float* vb2     = (const float*)d_in[20];
    float* out = (float*)d_out;

    const int TB = 256;
    const int enc_grid  = (N_NODES / 4 * 32 + TB - 1) / TB;   // 4 nodes/warp
    const int node_grid = (N_NODES + 31) / 32;                // 32 nodes/block
    const int seg_grid  = ((E_EDGES + 3) / 4 * 32 + TB - 1) / TB;  // 4 edges/warp
    const int eTB_grid  = (E_EDGES + TB - 1) / TB;

    encoder_kernel<<<enc_grid, TB>>>(x, enc_w, enc_b, enc_g, enc_bt,
                                     mlp_w1, mlp_b1);
    count_kernel<<<eTB_grid, TB>>>(ei);
    assign_kernel<<<(N_NODES + TB - 1) / TB, TB>>>();
    bucket_kernel<<<eTB_grid, TB>>>(ei, ea);

    for (int i = 0; i < NLAYERS; i++) {
        const float* w1 = mlp_w1 + (size_t)i * (HDIM + 3) * HH;
        const float* w2 = mlp_w2 + (size_t)i * HH * HDIM;
        const float* b2 = mlp_b2 + (size_t)i * HDIM;
        const float* lg = ln_g   + (size_t)i * HDIM;
        const float* lb = ln_b   + (size_t)i * HDIM;
        const float* w1n = mlp_w1 + (size_t)(i + 1) * (HDIM + 3) * HH;
        const float* b1n = mlp_b1 + (size_t)(i + 1) * HH;

        edge_seg_kernel<<<seg_grid, TB>>>(w1);

        if (i + 1 < NLAYERS)
            node_agg_kernel<false><<<node_grid, TB>>>(w2, b2, lg, lb, w1n, b1n,
                dw1, db1, dw2, db2, vw1, vb1, vw2, vb2, out);
        else
            node_agg_kernel<true ><<<node_grid, TB>>>(w2, b2, lg, lb, nullptr, nullptr,
                dw1, db1, dw2, db2, vw1, vb1, vw2, vb2, out);
    }
}

// round 8
// speedup vs baseline: 1.1660x; 1.1660x over previous
#include <cuda_runtime.h>
#include <cuda_bf16.h>

#define N_NODES 50000
#define E_EDGES 800000
#define IN_C    16
#define HDIM    64
#define HH      32
#define NLAYERS 3
#define FULL    0xffffffffu

typedef unsigned long long u64;

// Scratch (device globals; float4 for 16B alignment)
__device__ float  g_h[N_NODES * HDIM];   // row-major [n][64]
__device__ float4 g_p4[N_NODES * 8];     // row-major [n][32]
__device__ float4 g_q4[N_NODES * 8];     // row-major [n][32]
__device__ float  g_cnt[N_NODES];

// Packed k-pair weights: (w[2kp][j], w[2kp+1][j]) as u64
__device__ u64 g_w2p[NLAYERS * 16 * 64]; // [l][kp<16][j<64]
__device__ u64 g_w1p[NLAYERS * 32 * 32]; // [l][kp<32][j<32] (rows 0..63 of w1)
__device__ u64 g_dw1p[32 * 32];
__device__ u64 g_vw1p[32 * 32];

__device__ __forceinline__ u64 pack2(float lo, float hi) {
    u64 r;
    asm("mov.b64 %0, {%1, %2};" : "=l"(r) : "r"(__float_as_uint(lo)), "r"(__float_as_uint(hi)));
    return r;
}
__device__ __forceinline__ void unpack2(u64 v, float& lo, float& hi) {
    unsigned a, b;
    asm("mov.b64 {%0, %1}, %2;" : "=r"(a), "=r"(b) : "l"(v));
    lo = __uint_as_float(a); hi = __uint_as_float(b);
}
__device__ __forceinline__ u64 fma2(u64 a, u64 b, u64 c) {
    u64 d;
    asm("fma.rn.f32x2 %0, %1, %2, %3;" : "=l"(d) : "l"(a), "l"(b), "l"(c));
    return d;
}
__device__ __forceinline__ float pairsum(u64 v) {
    float lo, hi; unpack2(v, lo, hi); return lo + hi;
}
__device__ __forceinline__ void red_add_v4(float* ptr, float4 v) {
    asm volatile("red.global.add.v4.f32 [%0], {%1,%2,%3,%4};"
                 :: "l"(ptr), "f"(v.x), "f"(v.y), "f"(v.z), "f"(v.w) : "memory");
}

// ---------------- weight pack (once per run, ~8k threads) ----------------
__global__ void pack_kernel(const float* __restrict__ mlp_w1,
                            const float* __restrict__ mlp_w2,
                            const float* __restrict__ dw1,
                            const float* __restrict__ vw1)
{
    int idx = blockIdx.x * blockDim.x + threadIdx.x;
    if (idx < 3072) {                       // w2p: 3 * 16 * 64
        int l = idx / 1024, r = idx % 1024, kp = r / 64, j = r % 64;
        const float* w2 = mlp_w2 + (size_t)l * 32 * 64;
        g_w2p[idx] = pack2(w2[(2 * kp) * 64 + j], w2[(2 * kp + 1) * 64 + j]);
    } else if (idx < 6144) {                // w1p: 3 * 32 * 32
        int r2 = idx - 3072;
        int l = r2 / 1024, r = r2 % 1024, kp = r / 32, j = r % 32;
        const float* w1 = mlp_w1 + (size_t)l * 67 * 32;
        g_w1p[r2] = pack2(w1[(2 * kp) * 32 + j], w1[(2 * kp + 1) * 32 + j]);
    } else if (idx < 7168) {                // dw1p: 32 * 32
        int r = idx - 6144, kp = r / 32, j = r % 32;
        g_dw1p[r] = pack2(dw1[(2 * kp) * 32 + j], dw1[(2 * kp + 1) * 32 + j]);
    } else if (idx < 8192) {                // vw1p
        int r = idx - 7168, kp = r / 32, j = r % 32;
        g_vw1p[r] = pack2(vw1[(2 * kp) * 32 + j], vw1[(2 * kp + 1) * 32 + j]);
    }
}

// ---------------- encoder (R4, proven): h + p0 + zero q/cnt ----------------
__global__ __launch_bounds__(256) void encoder_kernel(
    const float* __restrict__ x,  const float* __restrict__ w,
    const float* __restrict__ b,  const float* __restrict__ g,
    const float* __restrict__ beta,
    const float* __restrict__ w1, const float* __restrict__ b1)
{
    int warp = (blockIdx.x * blockDim.x + threadIdx.x) >> 5;
    int lane = threadIdx.x & 31;
    int n0   = warp * 4;
    if (n0 >= N_NODES) return;

    float* g_p = (float*)g_p4;
    float* g_q = (float*)g_q4;

    float xv[4], a0[4], a1[4];
#pragma unroll
    for (int i = 0; i < 4; i++) {
        xv[i] = (lane < IN_C) ? x[(n0 + i) * IN_C + lane] : 0.0f;
        a0[i] = __ldg(&b[lane]);
        a1[i] = __ldg(&b[lane + 32]);
    }
#pragma unroll
    for (int k = 0; k < IN_C; k++) {
        float w0 = __ldg(&w[k * HDIM + lane]);
        float w1v = __ldg(&w[k * HDIM + 32 + lane]);
#pragma unroll
        for (int i = 0; i < 4; i++) {
            float xk = __shfl_sync(FULL, xv[i], k);
            a0[i] = fmaf(xk, w0, a0[i]);
            a1[i] = fmaf(xk, w1v, a1[i]);
        }
    }
    float gl = __ldg(&g[lane]), gh = __ldg(&g[lane + 32]);
    float bl = __ldg(&beta[lane]), bh = __ldg(&beta[lane + 32]);
    float h0[4], h1[4];
#pragma unroll
    for (int i = 0; i < 4; i++) {
        float s1 = a0[i] + a1[i], s2 = a0[i] * a0[i] + a1[i] * a1[i];
#pragma unroll
        for (int o = 16; o; o >>= 1) {
            s1 += __shfl_xor_sync(FULL, s1, o);
            s2 += __shfl_xor_sync(FULL, s2, o);
        }
        float mu  = s1 * (1.0f / 64.0f);
        float var = s2 * (1.0f / 64.0f) - mu * mu;
        float rs  = rsqrtf(var + 1e-5f);
        h0[i] = fmaxf(fmaf((a0[i] - mu) * rs, gl, bl), 0.0f);
        h1[i] = fmaxf(fmaf((a1[i] - mu) * rs, gh, bh), 0.0f);
        g_h[(n0 + i) * HDIM + lane]      = h0[i];
        g_h[(n0 + i) * HDIM + 32 + lane] = h1[i];
    }
    float acc[4];
#pragma unroll
    for (int i = 0; i < 4; i++) acc[i] = __ldg(&b1[lane]);
#pragma unroll
    for (int k = 0; k < 32; k++) {
        float wk = __ldg(&w1[k * HH + lane]);
#pragma unroll
        for (int i = 0; i < 4; i++)
            acc[i] = fmaf(__shfl_sync(FULL, h0[i], k), wk, acc[i]);
    }
#pragma unroll
    for (int k = 0; k < 32; k++) {
        float wk = __ldg(&w1[(32 + k) * HH + lane]);
#pragma unroll
        for (int i = 0; i < 4; i++)
            acc[i] = fmaf(__shfl_sync(FULL, h1[i], k), wk, acc[i]);
    }
#pragma unroll
    for (int i = 0; i < 4; i++) {
        g_p[(n0 + i) * HH + lane] = acc[i];
        g_q[(n0 + i) * HH + lane] = 0.0f;
    }
    if (lane < 4) g_cnt[n0 + lane] = 0.0f;
}

// ---------------- edge kernel (R4, proven; COUNT folds in-degree) ----------------
template<bool COUNT>
__global__ __launch_bounds__(256) void edge_kernel(
    const int* __restrict__ ei, const float* __restrict__ ea,
    const float* __restrict__ w1)
{
    int idx = blockIdx.x * blockDim.x + threadIdx.x;
    int e = idx >> 3, quad = idx & 7;
    if (e >= E_EDGES) return;

    int src = __ldg(&ei[e]);
    int dst = __ldg(&ei[E_EDGES + e]);
    float e0 = __ldg(&ea[e * 3 + 0]);
    float e1 = __ldg(&ea[e * 3 + 1]);
    float e2 = __ldg(&ea[e * 3 + 2]);

    float4 p = __ldg(&g_p4[src * 8 + quad]);
    const float4* W = (const float4*)(w1 + 64 * HH);
    float4 wa = __ldg(&W[quad]);
    float4 wb = __ldg(&W[8 + quad]);
    float4 wc = __ldg(&W[16 + quad]);

    float4 v;
    v.x = fmaxf(fmaf(e2, wc.x, fmaf(e1, wb.x, fmaf(e0, wa.x, p.x))), 0.0f);
    v.y = fmaxf(fmaf(e2, wc.y, fmaf(e1, wb.y, fmaf(e0, wa.y, p.y))), 0.0f);
    v.z = fmaxf(fmaf(e2, wc.z, fmaf(e1, wb.z, fmaf(e0, wa.z, p.z))), 0.0f);
    v.w = fmaxf(fmaf(e2, wc.w, fmaf(e1, wb.w, fmaf(e0, wa.w, p.w))), 0.0f);

    red_add_v4((float*)&g_q4[dst * 8 + quad], v);
    if (COUNT && quad == 0) atomicAdd(&g_cnt[dst], 1.0f);
}

// ---- stage-2 + mean + residual + LN; f32x2 GEMV loops; LAST fuses heads ----
template<bool LAST>
__global__ __launch_bounds__(256) void node_agg_kernel(
    int layer,
    const float* __restrict__ b2,
    const float* __restrict__ g,   const float* __restrict__ beta,
    const float* __restrict__ b1n,
    const float* __restrict__ db1, const float* __restrict__ dw2,
    const float* __restrict__ db2, const float* __restrict__ vb1,
    const float* __restrict__ vw2, const float* __restrict__ vb2,
    float* __restrict__ out)
{
    __shared__ __align__(16) float qbuf[32 * 36];   // [node][k<32], stride 36
    __shared__ __align__(16) float hbuf[32 * 68];   // [node][k<64], stride 68
    int t = threadIdx.x, w = t >> 5, lane = t & 31;
    int n0 = blockIdx.x * 32;
    int rem = N_NODES - n0; if (rem > 32) rem = 32;

    // stage q (direct padded copy, row-major both sides); zero q behind us
    {
        int nl = t >> 3, k0 = (t & 7) << 2;
        float4 v = make_float4(0.f, 0.f, 0.f, 0.f);
        float4* qp = (float4*)g_q4 + (size_t)n0 * 8 + t;
        if (nl < rem) { v = *qp; *qp = make_float4(0.f, 0.f, 0.f, 0.f); }
        *(float4*)&qbuf[nl * 36 + k0] = v;
    }
    __syncthreads();

    int nb = w * 4;   // this warp's nodes: n0+nb .. n0+nb+3

    // stage-2 GEMV via f32x2: lane j -> outputs (j, j+32)
    u64 aL[4] = {0, 0, 0, 0}, aH[4] = {0, 0, 0, 0};
    const u64* w2p = g_w2p + (size_t)layer * 16 * 64;
#pragma unroll
    for (int k4 = 0; k4 < 8; k4++) {          // 4 k's per iteration (2 kpairs)
        ulonglong2 q0 = *(const ulonglong2*)&qbuf[(nb + 0) * 36 + k4 * 4];
        ulonglong2 q1 = *(const ulonglong2*)&qbuf[(nb + 1) * 36 + k4 * 4];
        ulonglong2 q2 = *(const ulonglong2*)&qbuf[(nb + 2) * 36 + k4 * 4];
        ulonglong2 q3 = *(const ulonglong2*)&qbuf[(nb + 3) * 36 + k4 * 4];
        u64 wL0 = __ldg(&w2p[(2 * k4) * 64 + lane]);
        u64 wH0 = __ldg(&w2p[(2 * k4) * 64 + 32 + lane]);
        u64 wL1 = __ldg(&w2p[(2 * k4 + 1) * 64 + lane]);
        u64 wH1 = __ldg(&w2p[(2 * k4 + 1) * 64 + 32 + lane]);
        aL[0] = fma2(q0.x, wL0, aL[0]); aL[0] = fma2(q0.y, wL1, aL[0]);
        aH[0] = fma2(q0.x, wH0, aH[0]); aH[0] = fma2(q0.y, wH1, aH[0]);
        aL[1] = fma2(q1.x, wL0, aL[1]); aL[1] = fma2(q1.y, wL1, aL[1]);
        aH[1] = fma2(q1.x, wH0, aH[1]); aH[1] = fma2(q1.y, wH1, aH[1]);
        aL[2] = fma2(q2.x, wL0, aL[2]); aL[2] = fma2(q2.y, wL1, aL[2]);
        aH[2] = fma2(q2.x, wH0, aH[2]); aH[2] = fma2(q2.y, wH1, aH[2]);
        aL[3] = fma2(q3.x, wL0, aL[3]); aL[3] = fma2(q3.y, wL1, aL[3]);
        aH[3] = fma2(q3.x, wH0, aH[3]); aH[3] = fma2(q3.y, wH1, aH[3]);
    }
    float b2l = __ldg(&b2[lane]),  b2h = __ldg(&b2[32 + lane]);
    float gl  = __ldg(&g[lane]),   gh  = __ldg(&g[lane + 32]);
    float bl  = __ldg(&beta[lane]), bh = __ldg(&beta[lane + 32]);

    float h0[4], h1[4];
#pragma unroll
    for (int i = 0; i < 4; i++) {
        int n = n0 + nb + i;
        bool act = (nb + i) < rem;
        float c   = act ? g_cnt[n] : 0.f;
        float inv = (c > 0.f) ? (1.f / c) : 0.f;
        float has = (c > 0.f) ? 1.f : 0.f;
        float hh0 = act ? g_h[(size_t)n * HDIM + lane] : 0.f;
        float hh1 = act ? g_h[(size_t)n * HDIM + 32 + lane] : 0.f;
        float a0 = hh0 + pairsum(aL[i]) * inv + has * b2l;
        float a1 = hh1 + pairsum(aH[i]) * inv + has * b2h;
        float s1 = a0 + a1, s2 = a0 * a0 + a1 * a1;
#pragma unroll
        for (int o = 16; o; o >>= 1) {
            s1 += __shfl_xor_sync(FULL, s1, o);
            s2 += __shfl_xor_sync(FULL, s2, o);
        }
        float mu  = s1 * (1.f / 64.f);
        float var = s2 * (1.f / 64.f) - mu * mu;
        float rs  = rsqrtf(var + 1e-5f);
        h0[i] = fmaf((a0 - mu) * rs, gl, bl);
        h1[i] = fmaf((a1 - mu) * rs, gh, bh);
        if (!LAST && act) {
            g_h[(size_t)n * HDIM + lane]      = h0[i];
            g_h[(size_t)n * HDIM + 32 + lane] = h1[i];
        }
        // warp-local h buffer ([node][k] broadcast layout) — no block sync needed
        hbuf[(nb + i) * 68 + lane]      = h0[i];
        hbuf[(nb + i) * 68 + 32 + lane] = h1[i];
    }
    __syncwarp();

    if (!LAST) {
        // p_next = h_new @ W1n[:64] + b1n; lane j -> output j
        u64 a[4] = {0, 0, 0, 0};
        const u64* w1p = g_w1p + (size_t)(layer + 1) * 32 * 32;
#pragma unroll
        for (int k4 = 0; k4 < 16; k4++) {      // 4 k's per iteration
            ulonglong2 h0v = *(const ulonglong2*)&hbuf[(nb + 0) * 68 + k4 * 4];
            ulonglong2 h1v = *(const ulonglong2*)&hbuf[(nb + 1) * 68 + k4 * 4];
            ulonglong2 h2v = *(const ulonglong2*)&hbuf[(nb + 2) * 68 + k4 * 4];
            ulonglong2 h3v = *(const ulonglong2*)&hbuf[(nb + 3) * 68 + k4 * 4];
            u64 w0 = __ldg(&w1p[(2 * k4) * 32 + lane]);
            u64 w1v = __ldg(&w1p[(2 * k4 + 1) * 32 + lane]);
            a[0] = fma2(h0v.x, w0, a[0]); a[0] = fma2(h0v.y, w1v, a[0]);
            a[1] = fma2(h1v.x, w0, a[1]); a[1] = fma2(h1v.y, w1v, a[1]);
            a[2] = fma2(h2v.x, w0, a[2]); a[2] = fma2(h2v.y, w1v, a[2]);
            a[3] = fma2(h3v.x, w0, a[3]); a[3] = fma2(h3v.y, w1v, a[3]);
        }
        float bb = __ldg(&b1n[lane]);
        float* gp = (float*)g_p4;
#pragma unroll
        for (int i = 0; i < 4; i++)
            if ((nb + i) < rem)
                gp[(size_t)(n0 + nb + i) * HH + lane] = pairsum(a[i]) + bb;
    } else {
        // heads: lane j -> hidden unit j of each head
        u64 ad[4] = {0, 0, 0, 0}, av[4] = {0, 0, 0, 0};
#pragma unroll
        for (int k4 = 0; k4 < 16; k4++) {
            ulonglong2 h0v = *(const ulonglong2*)&hbuf[(nb + 0) * 68 + k4 * 4];
            ulonglong2 h1v = *(const ulonglong2*)&hbuf[(nb + 1) * 68 + k4 * 4];
            ulonglong2 h2v = *(const ulonglong2*)&hbuf[(nb + 2) * 68 + k4 * 4];
            ulonglong2 h3v = *(const ulonglong2*)&hbuf[(nb + 3) * 68 + k4 * 4];
            u64 dw0 = __ldg(&g_dw1p[(2 * k4) * 32 + lane]);
            u64 dw1v = __ldg(&g_dw1p[(2 * k4 + 1) * 32 + lane]);
            u64 vw0 = __ldg(&g_vw1p[(2 * k4) * 32 + lane]);
            u64 vw1v = __ldg(&g_vw1p[(2 * k4 + 1) * 32 + lane]);
            ad[0] = fma2(h0v.x, dw0, ad[0]); ad[0] = fma2(h0v.y, dw1v, ad[0]);
            av[0] = fma2(h0v.x, vw0, av[0]); av[0] = fma2(h0v.y, vw1v, av[0]);
            ad[1] = fma2(h1v.x, dw0, ad[1]); ad[1] = fma2(h1v.y, dw1v, ad[1]);
            av[1] = fma2(h1v.x, vw0, av[1]); av[1] = fma2(h1v.y, vw1v, av[1]);
            ad[2] = fma2(h2v.x, dw0, ad[2]); ad[2] = fma2(h2v.y, dw1v, ad[2]);
            av[2] = fma2(h2v.x, vw0, av[2]); av[2] = fma2(h2v.y, vw1v, av[2]);
            ad[3] = fma2(h3v.x, dw0, ad[3]); ad[3] = fma2(h3v.y, dw1v, ad[3]);
            av[3] = fma2(h3v.x, vw0, av[3]); av[3] = fma2(h3v.y, vw1v, av[3]);
        }
        float dbi = __ldg(&db1[lane]), vbi = __ldg(&vb1[lane]);
        float w2d  = __ldg(&dw2[lane]);
        float w2v0 = __ldg(&vw2[lane * 2 + 0]);
        float w2v1 = __ldg(&vw2[lane * 2 + 1]);
#pragma unroll
        for (int i = 0; i < 4; i++) {
            float rd = fmaxf(pairsum(ad[i]) + dbi, 0.f);
            float rv = fmaxf(pairsum(av[i]) + vbi, 0.f);
            float d  = rd * w2d;
            float v0 = rv * w2v0;
            float v1 = rv * w2v1;
#pragma unroll
            for (int o = 16; o; o >>= 1) {
                d  += __shfl_xor_sync(FULL, d, o);
                v0 += __shfl_xor_sync(FULL, v0, o);
                v1 += __shfl_xor_sync(FULL, v1, o);
            }
            int n = n0 + nb + i;
            if (lane == 0 && (nb + i) < rem) {
                out[n] = d + __ldg(&db2[0]);
                float2* vout = (float2*)(out + N_NODES);
                vout[n] = make_float2(v0 + __ldg(&vb2[0]), v1 + __ldg(&vb2[1]));
            }
        }
    }
}

// ---------------- launch ----------------
extern "C" void kernel_launch(void* const* d_in, const int* in_sizes, int n_in,
                              void* d_out, int out_size)
{
    const float* x       = (const float*)d_in[0];
    const int*   ei      = (const int*)  d_in[1];
    const float* ea      = (const float*)d_in[2];
    const float* enc_w   = (const float*)d_in[3];
    const float* enc_b   = (const float*)d_in[4];
    const float* enc_g   = (const float*)d_in[5];
    const float* enc_bt  = (const float*)d_in[6];
    const float* mlp_w1  = (const float*)d_in[7];   // [L, 67, 32]
    const float* mlp_b1  = (const float*)d_in[8];   // [L, 32]
    const float* mlp_w2  = (const float*)d_in[9];   // [L, 32, 64]
    const float* mlp_b2  = (const float*)d_in[10];  // [L, 64]
    const float* ln_g    = (const float*)d_in[11];  // [L, 64]
    const float* ln_b    = (const float*)d_in[12];  // [L, 64]
    const float* dw1     = (const float*)d_in[13];
    const float* db1     = (const float*)d_in[14];
    const float* dw2     = (const float*)d_in[15];
    const float* db2     = (const float*)d_in[16];
    const float* vw1     = (const float*)d_in[17];
    const float* vb1     = (const float*)d_in[18];
    const float* vw2     = (const float*)d_in[19];
    const float* vb2     = (const float*)d_in[20];
    float* out = (float*)d_out;

    const int TB = 256;
    const int enc_grid  = (N_NODES / 4 * 32 + TB - 1) / TB;   // 4 nodes/warp
    const int node_grid = (N_NODES + 31) / 32;                // 32 nodes/block
    const int edge_grid = (E_EDGES * 8 + TB - 1) / TB;        // 8 threads/edge

    pack_kernel<<<32, TB>>>(mlp_w1, mlp_w2, dw1, vw1);
    encoder_kernel<<<enc_grid, TB>>>(x, enc_w, enc_b, enc_g, enc_bt,
                                     mlp_w1, mlp_b1);

    for (int i = 0; i < NLAYERS; i++) {
        const float* w1 = mlp_w1 + (size_t)i * (HDIM + 3) * HH;
        const float* b2 = mlp_b2 + (size_t)i * HDIM;
        const float* lg = ln_g   + (size_t)i * HDIM;
        const float* lb = ln_b   + (size_t)i * HDIM;
        const float* b1n = mlp_b1 + (size_t)(i + 1) * HH;

        if (i == 0) edge_kernel<true ><<<edge_grid, TB>>>(ei, ea, w1);
        else        edge_kernel<false><<<edge_grid, TB>>>(ei, ea, w1);

        if (i + 1 < NLAYERS)
            node_agg_kernel<false><<<node_grid, TB>>>(i, b2, lg, lb, b1n,
                db1, dw2, db2, vb1, vw2, vb2, out);
        else
            node_agg_kernel<true ><<<node_grid, TB>>>(i, b2, lg, lb, nullptr,
                db1, dw2, db2, vb1, vw2, vb2, out);
    }
}